// round 17
// baseline (speedup 1.0000x reference)
#include <cuda_runtime.h>
#include <cuda_fp16.h>
#include <cstdint>

#define EMA_OLD 0.01f
#define EMA_NEW 0.99f

#define MAXB 4096
#define MAXN 1024
#define MAXD 4096
#define AMB_CAP 262144
#define NBLK 8                       // n / BN

__device__ float              g_d2[(size_t)MAXB * MAXN];     // approx distances
__device__ unsigned long long g_blockmin[MAXB * NBLK];       // per 128-col block packed min
__device__ unsigned long long g_bestex[MAXB];                // exact rescore results
__device__ int                g_winner[MAXN];
__device__ float              g_mnorm[MAXN];
__device__ __half             g_y16[(size_t)MAXB * MAXD];
__device__ __half             g_m16[(size_t)MAXN * MAXD];
__device__ int                g_amb_cnt;
__device__ unsigned           g_amb[AMB_CAP];                // (b<<10)|j

// ---------------------------------------------------------------------------
__device__ __forceinline__ uint32_t pack_h2(float lo, float hi) {
    uint32_t d;
    asm("cvt.rn.f16x2.f32 %0, %1, %2;" : "=r"(d) : "f"(hi), "f"(lo));
    return d;
}

// ---------------------------------------------------------------------------
// Fused conversion kernel: blocks [0, yblocks) convert Y (+ scratch init);
// blocks [yblocks, yblocks+n) convert M row j and compute ||m_j||^2.
// ---------------------------------------------------------------------------
__global__ __launch_bounds__(256)
void conv_all_kernel(const float* __restrict__ Y,
                     const float* __restrict__ M,
                     size_t total8, int yblocks, int D, int B, int n) {
    if ((int)blockIdx.x < yblocks) {
        size_t i = (size_t)blockIdx.x * 256 + threadIdx.x;
        if (i < (size_t)(B * NBLK)) g_blockmin[i] = 0xFFFFFFFFFFFFFFFFull;
        if (i < (size_t)B) g_bestex[i] = 0xFFFFFFFFFFFFFFFFull;
        if (i < (size_t)n) g_winner[i] = -1;
        if (i == 0) g_amb_cnt = 0;

        if (i >= total8) return;
        const float4* src = (const float4*)Y + 2 * i;
        float4 a = src[0], b = src[1];
        uint4 o;
        o.x = pack_h2(a.x, a.y);
        o.y = pack_h2(a.z, a.w);
        o.z = pack_h2(b.x, b.y);
        o.w = pack_h2(b.z, b.w);
        ((uint4*)g_y16)[i] = o;
    } else {
        int j = (int)blockIdx.x - yblocks;
        const float* row = M + (size_t)j * D;
        float s = 0.f;
        for (int t = threadIdx.x; t < D / 8; t += 256) {
            const float4* src = (const float4*)row + 2 * t;
            float4 a = src[0], b = src[1];
            s = fmaf(a.x, a.x, s); s = fmaf(a.y, a.y, s);
            s = fmaf(a.z, a.z, s); s = fmaf(a.w, a.w, s);
            s = fmaf(b.x, b.x, s); s = fmaf(b.y, b.y, s);
            s = fmaf(b.z, b.z, s); s = fmaf(b.w, b.w, s);
            uint4 o;
            o.x = pack_h2(a.x, a.y);
            o.y = pack_h2(a.z, a.w);
            o.z = pack_h2(b.x, b.y);
            o.w = pack_h2(b.z, b.w);
            ((uint4*)(g_m16 + (size_t)j * D))[t] = o;
        }
        __shared__ float sh[256];
        sh[threadIdx.x] = s;
        __syncthreads();
        for (int off = 128; off > 0; off >>= 1) {
            if (threadIdx.x < off) sh[threadIdx.x] += sh[threadIdx.x + off];
            __syncthreads();
        }
        if (threadIdx.x == 0) g_mnorm[j] = sh[0];
    }
}

// ===========================================================================
// Phase 1: fp16 mma.sync (m16n8k16) GEMM on pre-converted f16 data.
// CTA 128x128, BK=32(f16), 128 threads = 4 warps (2M x 2N); warp tile 64x64.
// cp.async 4-stage (wait_group 2); ldmatrix.x4 fragments; paired-row SW128.
// ===========================================================================
#define BM 128
#define BN 128
#define BK 32
#define NSTAGE 4

#define TILE_BYTES 8192
#define STAGE_BYTES 16384
#define S_B 8192
#define S_MN (NSTAGE * STAGE_BYTES)
#define SMEM_TOT (S_MN + 512)

__device__ __forceinline__ uint32_t tbyte(uint32_t r, uint32_t koff) {
    uint32_t b = (r & 63u) * 128u + (r >> 6) * 64u + koff;
    return b ^ ((b >> 3) & 0x70u);   // SW128
}
__device__ __forceinline__ uint32_t smem_u32(const void* p) {
    uint32_t a;
    asm("{ .reg .u64 t; cvta.to.shared.u64 t, %1; cvt.u32.u64 %0, t; }" : "=r"(a) : "l"(p));
    return a;
}
__device__ __forceinline__ void mma16(float* d, const uint32_t* a, const uint32_t* b) {
    asm volatile(
        "mma.sync.aligned.m16n8k16.row.col.f32.f16.f16.f32 "
        "{%0,%1,%2,%3}, {%4,%5,%6,%7}, {%8,%9}, {%0,%1,%2,%3};"
        : "+f"(d[0]), "+f"(d[1]), "+f"(d[2]), "+f"(d[3])
        : "r"(a[0]), "r"(a[1]), "r"(a[2]), "r"(a[3]), "r"(b[0]), "r"(b[1]));
}
__device__ __forceinline__ void ldsm_x4(uint32_t* r, uint32_t addr) {
    asm volatile(
        "ldmatrix.sync.aligned.m8n8.x4.shared.b16 {%0,%1,%2,%3}, [%4];"
        : "=r"(r[0]), "=r"(r[1]), "=r"(r[2]), "=r"(r[3]) : "r"(addr));
}
#define CP_ASYNC16(dst, src) \
    asm volatile("cp.async.cg.shared.global [%0], [%1], 16;" :: "r"(dst), "l"(src))
#define CP_COMMIT() asm volatile("cp.async.commit_group;")
#define CP_WAIT2()  asm volatile("cp.async.wait_group 2;")

__device__ __forceinline__ unsigned fkey(float f) {
    unsigned u = __float_as_uint(f);
    return (u & 0x80000000u) ? ~u : (u | 0x80000000u);
}
__device__ __forceinline__ float unfkey(unsigned k) {
    unsigned u = (k & 0x80000000u) ? (k ^ 0x80000000u) : ~k;
    return __uint_as_float(u);
}
__device__ __forceinline__ unsigned long long umin64(unsigned long long a,
                                                     unsigned long long b) {
    return a < b ? a : b;
}

__global__ __launch_bounds__(128, 2)
void gemm_d2_mma(int D, int n) {
    extern __shared__ __align__(1024) char smem[];
    const uint32_t sbase = smem_u32(smem);
    const int tid  = threadIdx.x;
    const int lane = tid & 31;
    const int wid  = tid >> 5;
    const int wm   = wid >> 1;
    const int wn   = wid & 1;
    const int brow = blockIdx.y * BM;
    const int bcol = blockIdx.x * BN;
    const int blk  = blockIdx.x;

    float* sh_mn = (float*)(smem + S_MN);
    if (tid < 128) sh_mn[tid] = g_mnorm[bcol + tid];

    uint32_t soff[4];
    int goff[4];
#pragma unroll
    for (int i = 0; i < 4; i++) {
        int l = tid + 128 * i;
        int row = l >> 2;
        int kl = l & 3;
        soff[i] = tbyte((uint32_t)row, (uint32_t)kl * 16);
        goff[i] = row * D + kl * 8;
    }
    const __half* Yb = g_y16 + (size_t)brow * D;
    const __half* Mb = g_m16 + (size_t)bcol * D;

    float acc[4][8][4];
#pragma unroll
    for (int mt = 0; mt < 4; mt++)
#pragma unroll
        for (int nt = 0; nt < 8; nt++)
#pragma unroll
            for (int q = 0; q < 4; q++) acc[mt][nt][q] = 0.f;

    const int NK = D / BK;

#pragma unroll
    for (int c = 0; c < 3; c++) {
        const uint32_t sb = sbase + (uint32_t)c * STAGE_BYTES;
#pragma unroll
        for (int i = 0; i < 4; i++) {
            CP_ASYNC16(sb + soff[i], Yb + goff[i] + c * BK);
            CP_ASYNC16(sb + S_B + soff[i], Mb + goff[i] + c * BK);
        }
        CP_COMMIT();
    }

    const uint32_t a_row = (uint32_t)(wm * 64 + (lane & 15));
    const uint32_t a_seg = (uint32_t)(lane >> 4) * 16;
    const uint32_t b_row = (uint32_t)(wn * 64 + ((lane >> 4) << 3) + (lane & 7));
    const uint32_t b_seg = (uint32_t)((lane >> 3) & 1) * 16;

    int stage = 0;
    for (int kc = 0; kc < NK; kc++) {
        CP_WAIT2();
        __syncthreads();

        if (kc + 3 < NK) {
            int s3 = stage + 3;
            if (s3 >= NSTAGE) s3 -= NSTAGE;
            const uint32_t sb = sbase + (uint32_t)s3 * STAGE_BYTES;
            const int ko = (kc + 3) * BK;
#pragma unroll
            for (int i = 0; i < 4; i++) {
                CP_ASYNC16(sb + soff[i], Yb + goff[i] + ko);
                CP_ASYNC16(sb + S_B + soff[i], Mb + goff[i] + ko);
            }
        }
        CP_COMMIT();

        const uint32_t sa = sbase + (uint32_t)stage * STAGE_BYTES;
        const uint32_t sb_ = sa + S_B;
#pragma unroll
        for (int ks = 0; ks < 2; ks++) {
            const uint32_t kbase = (uint32_t)(ks * 32);

            uint32_t ah[4][4];
#pragma unroll
            for (int mt = 0; mt < 4; mt++)
                ldsm_x4(ah[mt], sa + tbyte(a_row + (uint32_t)(mt * 16),
                                           kbase + a_seg));
            uint32_t bh[4][4];
#pragma unroll
            for (int np = 0; np < 4; np++)
                ldsm_x4(bh[np], sb_ + tbyte(b_row + (uint32_t)(np * 16),
                                            kbase + b_seg));
#pragma unroll
            for (int mt = 0; mt < 4; mt++)
#pragma unroll
                for (int np = 0; np < 4; np++) {
                    mma16(acc[mt][2 * np],     ah[mt], &bh[np][0]);
                    mma16(acc[mt][2 * np + 1], ah[mt], &bh[np][2]);
                }
        }

        stage = (stage + 1 >= NSTAGE) ? 0 : stage + 1;
    }

    // ---- epilogue: d2 store + per-(row, 128-col-block) packed min ----
#pragma unroll
    for (int mt = 0; mt < 4; mt++) {
        int r0 = brow + wm * 64 + mt * 16 + (lane >> 2);
        unsigned long long pk0 = 0xFFFFFFFFFFFFFFFFull;
        unsigned long long pk1 = 0xFFFFFFFFFFFFFFFFull;
#pragma unroll
        for (int nt = 0; nt < 8; nt++) {
            int cl = wn * 64 + nt * 8 + (lane & 3) * 2;
            float mn0 = sh_mn[cl], mn1 = sh_mn[cl + 1];
            float2 p0, p1;
            p0.x = fmaf(-2.0f, acc[mt][nt][0], mn0);
            p0.y = fmaf(-2.0f, acc[mt][nt][1], mn1);
            p1.x = fmaf(-2.0f, acc[mt][nt][2], mn0);
            p1.y = fmaf(-2.0f, acc[mt][nt][3], mn1);
            size_t base = (size_t)r0 * n + (bcol + cl);
            *(float2*)&g_d2[base] = p0;
            *(float2*)&g_d2[base + (size_t)8 * n] = p1;
            unsigned j0 = (unsigned)(bcol + cl), j1 = j0 + 1;
            pk0 = umin64(pk0, ((unsigned long long)fkey(p0.x) << 32) | j0);
            pk0 = umin64(pk0, ((unsigned long long)fkey(p0.y) << 32) | j1);
            pk1 = umin64(pk1, ((unsigned long long)fkey(p1.x) << 32) | j0);
            pk1 = umin64(pk1, ((unsigned long long)fkey(p1.y) << 32) | j1);
        }
#pragma unroll
        for (int off = 1; off < 4; off <<= 1) {
            pk0 = umin64(pk0, __shfl_xor_sync(0xFFFFFFFFu, pk0, off));
            pk1 = umin64(pk1, __shfl_xor_sync(0xFFFFFFFFu, pk1, off));
        }
        if ((lane & 3) == 0) {
            atomicMin(&g_blockmin[r0 * NBLK + blk], pk0);
            atomicMin(&g_blockmin[(r0 + 8) * NBLK + blk], pk1);
        }
    }
}

// ===========================================================================
// Phase 2a: warp-per-row hierarchical scan (block minima -> lazy d2 scan).
// ===========================================================================
#define SEL_EPS 4.0f
#define SCAN_WPB 4
#define SCAN_CAND 16

__global__ __launch_bounds__(SCAN_WPB * 32)
void select_scan(int n) {
    const int lane = threadIdx.x & 31;
    const int wloc = threadIdx.x >> 5;
    const int b = blockIdx.x * SCAN_WPB + wloc;

    __shared__ unsigned scand[SCAN_WPB][SCAN_CAND];
    __shared__ int scnt[SCAN_WPB];
    if (lane == 0) scnt[wloc] = 0;
    __syncwarp();

    unsigned long long pk = 0xFFFFFFFFFFFFFFFFull;
    if (lane < NBLK) pk = __ldg(&g_blockmin[b * NBLK + lane]);
    unsigned long long gb = pk;
#pragma unroll
    for (int off = 4; off > 0; off >>= 1)
        gb = umin64(gb, __shfl_xor_sync(0xFFFFFFFFu, gb, off));
    gb = __shfl_sync(0xFFFFFFFFu, gb, 0);
    const int jstar = (int)(gb & 0xFFFFFFFFull);
    const float thr = unfkey((unsigned)(gb >> 32)) + SEL_EPS;

    int total = 0;
#pragma unroll
    for (int blk = 0; blk < NBLK; blk++) {
        unsigned long long bm = __shfl_sync(0xFFFFFFFFu, pk, blk);
        if (unfkey((unsigned)(bm >> 32)) > thr) continue;
        float4 v = *(const float4*)(g_d2 + (size_t)b * n + blk * 128 + lane * 4);
        int c = (v.x <= thr) + (v.y <= thr) + (v.z <= thr) + (v.w <= thr);
        if (c) {
            int base = atomicAdd(&scnt[wloc], c);
            int idx = blk * 128 + lane * 4;
            if (v.x <= thr && base < SCAN_CAND) scand[wloc][base++] = (unsigned)idx;
            if (v.y <= thr && base < SCAN_CAND) scand[wloc][base++] = (unsigned)(idx + 1);
            if (v.z <= thr && base < SCAN_CAND) scand[wloc][base++] = (unsigned)(idx + 2);
            if (v.w <= thr && base < SCAN_CAND) scand[wloc][base++] = (unsigned)(idx + 3);
        }
        total += c;
    }
#pragma unroll
    for (int off = 16; off > 0; off >>= 1)
        total += __shfl_xor_sync(0xFFFFFFFFu, total, off);
    __syncwarp();

    if (lane == 0) {
        if (total <= 1) {
            atomicMax(&g_winner[jstar], b);
        } else {
            int cnum = scnt[wloc] < SCAN_CAND ? scnt[wloc] : SCAN_CAND;
            int pos = atomicAdd(&g_amb_cnt, cnum);
            for (int i = 0; i < cnum && pos + i < AMB_CAP; i++)
                g_amb[pos + i] = ((unsigned)b << 10) | scand[wloc][i];
        }
    }
}

// ===========================================================================
// Phase 2b: block-per-candidate exact fp32 rescore (256 thr, unrolled MLP-8).
// 2048 blocks: nearly all blocks handle <= 1 candidate.
// ===========================================================================
__global__ __launch_bounds__(256)
void rescore_kernel(const float* __restrict__ Y,
                    const float* __restrict__ M,
                    int D) {
    const int tid = threadIdx.x;
    const int cnt = g_amb_cnt < AMB_CAP ? g_amb_cnt : AMB_CAP;
    __shared__ float sw[8];

    for (int e = blockIdx.x; e < cnt; e += gridDim.x) {
        unsigned ent = g_amb[e];
        int b = (int)(ent >> 10);
        int j = (int)(ent & 1023u);
        const float4* yrow = (const float4*)(Y + (size_t)b * D) + tid;
        const float4* mrow = (const float4*)(M + (size_t)j * D) + tid;
        // D=4096 -> 1024 float4; 256 threads -> 4 per thread; fully unrolled
        float4 yv0 = yrow[0],   mv0 = mrow[0];
        float4 yv1 = yrow[256], mv1 = mrow[256];
        float4 yv2 = yrow[512], mv2 = mrow[512];
        float4 yv3 = yrow[768], mv3 = mrow[768];
        float p0 = 0.f, p1 = 0.f, p2 = 0.f, p3 = 0.f;
        p0 = fmaf(yv0.x, mv0.x, p0); p1 = fmaf(yv0.y, mv0.y, p1);
        p2 = fmaf(yv0.z, mv0.z, p2); p3 = fmaf(yv0.w, mv0.w, p3);
        p0 = fmaf(yv1.x, mv1.x, p0); p1 = fmaf(yv1.y, mv1.y, p1);
        p2 = fmaf(yv1.z, mv1.z, p2); p3 = fmaf(yv1.w, mv1.w, p3);
        p0 = fmaf(yv2.x, mv2.x, p0); p1 = fmaf(yv2.y, mv2.y, p1);
        p2 = fmaf(yv2.z, mv2.z, p2); p3 = fmaf(yv2.w, mv2.w, p3);
        p0 = fmaf(yv3.x, mv3.x, p0); p1 = fmaf(yv3.y, mv3.y, p1);
        p2 = fmaf(yv3.z, mv3.z, p2); p3 = fmaf(yv3.w, mv3.w, p3);
        float p = (p0 + p1) + (p2 + p3);
#pragma unroll
        for (int off = 16; off > 0; off >>= 1)
            p += __shfl_xor_sync(0xFFFFFFFFu, p, off);
        if ((tid & 31) == 0) sw[tid >> 5] = p;
        __syncthreads();
        if (tid == 0) {
            float dot = ((sw[0] + sw[1]) + (sw[2] + sw[3])) +
                        ((sw[4] + sw[5]) + (sw[6] + sw[7]));
            float s = fmaf(-2.0f, dot, g_mnorm[j]);
            unsigned long long pk =
                ((unsigned long long)fkey(s) << 32) | (unsigned)j;
            atomicMin(&g_bestex[b], pk);
        }
        __syncthreads();
    }
}

// Phase 2c: apply exact winners for ambiguous rows.
__global__ void finalize_kernel(int B) {
    int b = blockIdx.x * blockDim.x + threadIdx.x;
    if (b < B) {
        unsigned long long v = g_bestex[b];
        if (v != 0xFFFFFFFFFFFFFFFFull)
            atomicMax(&g_winner[(int)(v & 0xFFFFFFFFull)], b);
    }
}

// ---------------------------------------------------------------------------
__global__ void output_kernel(const float* __restrict__ Y,
                              const float* __restrict__ M,
                              const float* __restrict__ SD,
                              float* __restrict__ out,
                              int D, int n) {
    int j = blockIdx.x;
    int w = g_winner[j];
    int D4 = D >> 2;
    const float4* mrow  = (const float4*)(M  + (size_t)j * D);
    const float4* sdrow = (const float4*)(SD + (size_t)j * D);
    float4* om = (float4*)(out + (size_t)j * D);
    float4* os = (float4*)(out + (size_t)(n + j) * D);

    if (w < 0) {
        for (int d = threadIdx.x; d < D4; d += blockDim.x) {
            om[d] = mrow[d];
            os[d] = sdrow[d];
        }
    } else {
        const float4* yrow = (const float4*)(Y + (size_t)w * D);
        for (int d = threadIdx.x; d < D4; d += blockDim.x) {
            float4 mv = mrow[d], yv = yrow[d], sv = sdrow[d];
            float4 nm, ns;
            nm.x = mv.x * EMA_OLD + yv.x * EMA_NEW;
            nm.y = mv.y * EMA_OLD + yv.y * EMA_NEW;
            nm.z = mv.z * EMA_OLD + yv.z * EMA_NEW;
            nm.w = mv.w * EMA_OLD + yv.w * EMA_NEW;
            float dx = nm.x - yv.x, dy = nm.y - yv.y,
                  dz = nm.z - yv.z, dw = nm.w - yv.w;
            ns.x = dx * dx * EMA_OLD + sv.x * EMA_NEW;
            ns.y = dy * dy * EMA_OLD + sv.y * EMA_NEW;
            ns.z = dz * dz * EMA_OLD + sv.z * EMA_NEW;
            ns.w = dw * dw * EMA_OLD + sv.w * EMA_NEW;
            om[d] = nm;
            os[d] = ns;
        }
    }
}

// ---------------------------------------------------------------------------
extern "C" void kernel_launch(void* const* d_in, const int* in_sizes, int n_in,
                              void* d_out, int out_size) {
    const float* y  = (const float*)d_in[0];
    const float* m  = (const float*)d_in[1];
    const float* sd = (const float*)d_in[2];
    (void)n_in; (void)out_size;

    const int n = in_sizes[3];            // 1024
    const int D = in_sizes[1] / n;        // 4096
    const int B = in_sizes[0] / D;        // 4096
    float* out = (float*)d_out;

    size_t y8 = (size_t)B * D / 8;
    int yblocks = (int)((y8 + 255) / 256);
    conv_all_kernel<<<yblocks + n, 256>>>(y, m, y8, yblocks, D, B, n);

    cudaFuncSetAttribute(gemm_d2_mma,
                         cudaFuncAttributeMaxDynamicSharedMemorySize, SMEM_TOT);
    dim3 grid(n / BN, B / BM);
    gemm_d2_mma<<<grid, 128, SMEM_TOT>>>(D, n);

    select_scan<<<B / SCAN_WPB, SCAN_WPB * 32>>>(n);
    rescore_kernel<<<2048, 256>>>(y, m, D);
    finalize_kernel<<<(B + 255) / 256, 256>>>(B);
    output_kernel<<<n, 256>>>(y, m, sd, out, D, n);
}